// round 6
// baseline (speedup 1.0000x reference)
#include <cuda_runtime.h>
#include <cuda_bf16.h>

#define NN 50000
#define EE 800000
#define GG 256
#define FMAX 128
#define NB_SCAN 49   // ceil(50000/1024)

// stat offsets: L1=0(16) L2=128(32) L3=256(64) L4=384(64) L5=512(128)
__device__ unsigned long long g_pack[NN];   // count<<42 | weightsum_fx32
__device__ float  g_dis[NN];
__device__ int    g_rowptr[NN + 1];
__device__ int    g_blocksum[64];
__device__ int    g_bar1, g_bar2;
__device__ int    g_src[EE];
__device__ float  g_wn[EE];
__device__ float  g_bufA[NN * FMAX];
__device__ float  g_bufB[NN * 64];
__device__ float  g_m[NN * 16];
__device__ double g_sum[640];
__device__ double g_sq[640];
__device__ float  g_pooled[GG * FMAX];

// ---------------- preprocessing ----------------
__global__ void init_kernel() {
    int i = blockIdx.x * blockDim.x + threadIdx.x;
    if (i < NN) g_pack[i] = 0ULL;
    if (i < GG * FMAX) g_pooled[i] = 0.0f;
    if (i < 640) { g_sum[i] = 0.0; g_sq[i] = 0.0; }
    if (i == 0) { g_bar1 = 0; g_bar2 = 0; }
}

__global__ void count_kernel(const int* __restrict__ ei, const float* __restrict__ ew) {
    int e = blockIdx.x * blockDim.x + threadIdx.x;
    if (e < EE) {
        int c = ei[EE + e];
        unsigned long long p = (1ULL << 42) |
            (unsigned long long)(ew[e] * 4294967296.0f);
        atomicAdd(&g_pack[c], p);
    }
}

__device__ __forceinline__ void gbar(int* ctr) {
    __syncthreads();
    if (threadIdx.x == 0) {
        __threadfence();
        atomicAdd(ctr, 1);
        while (atomicAdd(ctr, 0) < NB_SCAN) __nanosleep(32);
    }
    __syncthreads();
}

// one kernel: dis + local scan -> global offsets -> scatter (vectorized)
__global__ __launch_bounds__(1024)
void csr_kernel(const int* __restrict__ ei, const float* __restrict__ ew) {
    __shared__ int s[1024];
    __shared__ int soff;
    int t = threadIdx.x;
    int i = blockIdx.x * 1024 + t;
    unsigned long long p = (i < NN) ? g_pack[i] : 0ULL;
    int v = (int)(p >> 42);
    s[t] = v;
    if (i < NN) {
        double wfx = (double)(p & ((1ULL << 42) - 1ULL)) * 2.3283064365386963e-10;
        g_dis[i] = rsqrtf((float)(1.0 + wfx));
    }
    __syncthreads();
    #pragma unroll
    for (int off = 1; off < 1024; off <<= 1) {
        int x = (t >= off) ? s[t - off] : 0;
        __syncthreads();
        s[t] += x;
        __syncthreads();
    }
    int local_excl = s[t] - v;
    if (t == 1023) g_blocksum[blockIdx.x] = s[1023];

    gbar(&g_bar1);

    if (t == 0) {
        int off = 0;
        for (int b = 0; b < blockIdx.x; b++) off += g_blocksum[b];
        soff = off;
    }
    __syncthreads();
    if (i < NN) g_rowptr[i] = soff + local_excl;

    gbar(&g_bar2);

    // scatter: 4 edges per thread per pass (EE % 4 == 0)
    const int nth4 = NB_SCAN * 1024 * 4;
    for (int base = (blockIdx.x * 1024 + t) * 4; base < EE; base += nth4) {
        int4   r4 = *(const int4*)(ei + base);
        int4   c4 = *(const int4*)(ei + EE + base);
        float4 w4 = *(const float4*)(ew + base);
        float dr0 = __ldcg(&g_dis[r4.x]), dc0 = __ldcg(&g_dis[c4.x]);
        float dr1 = __ldcg(&g_dis[r4.y]), dc1 = __ldcg(&g_dis[c4.y]);
        float dr2 = __ldcg(&g_dis[r4.z]), dc2 = __ldcg(&g_dis[c4.z]);
        float dr3 = __ldcg(&g_dis[r4.w]), dc3 = __ldcg(&g_dis[c4.w]);
        int p0 = atomicAdd(&g_rowptr[c4.x], 1);
        int p1 = atomicAdd(&g_rowptr[c4.y], 1);
        int p2 = atomicAdd(&g_rowptr[c4.z], 1);
        int p3 = atomicAdd(&g_rowptr[c4.w], 1);
        g_src[p0] = r4.x;  g_wn[p0] = dr0 * w4.x * dc0;
        g_src[p1] = r4.y;  g_wn[p1] = dr1 * w4.y * dc1;
        g_src[p2] = r4.z;  g_wn[p2] = dr2 * w4.z * dc2;
        g_src[p3] = r4.w;  g_wn[p3] = dr3 * w4.w * dc3;
    }
}

// ---------------- L1 matmul: m = x @ W1 ----------------
template <int DIN, int DOUT, int TILE>
__global__ __launch_bounds__(256)
void matmul_plain_kernel(const float* __restrict__ h, const float* __restrict__ W,
                         float* __restrict__ out) {
    constexpr int CG = DOUT / 4;
    constexpr int RG = 256 / CG;
    constexpr int RPT = TILE / RG;
    extern __shared__ float smem[];
    float* sW = smem;
    float* sH = smem + DIN * DOUT;
    int t = threadIdx.x;
    int node0 = blockIdx.x * TILE;
    for (int i = t; i < DIN * DOUT / 4; i += 256)
        ((float4*)sW)[i] = ((const float4*)W)[i];
    for (int i = t; i < TILE * DIN / 4; i += 256) {
        int nn = node0 + (i * 4) / DIN;
        float4 v = make_float4(0.f, 0.f, 0.f, 0.f);
        if (nn < NN) v = ((const float4*)h)[nn * (DIN / 4) + ((i * 4) % DIN) / 4];
        ((float4*)sH)[i] = v;
    }
    __syncthreads();
    int cg = t % CG, rg = t / CG;
    float acc[RPT][4];
    #pragma unroll
    for (int r = 0; r < RPT; r++) { acc[r][0]=0.f; acc[r][1]=0.f; acc[r][2]=0.f; acc[r][3]=0.f; }
    const float* sHr = sH + rg * RPT * DIN;
    #pragma unroll 8
    for (int k = 0; k < DIN; k++) {
        float4 wv = *(const float4*)(sW + k * DOUT + cg * 4);
        #pragma unroll
        for (int r = 0; r < RPT; r++) {
            float hv = sHr[r * DIN + k];
            acc[r][0] += hv * wv.x; acc[r][1] += hv * wv.y;
            acc[r][2] += hv * wv.z; acc[r][3] += hv * wv.w;
        }
    }
    #pragma unroll
    for (int r = 0; r < RPT; r++) {
        int node = node0 + rg * RPT + r;
        if (node < NN)
            ((float4*)out)[node * (DOUT / 4) + cg] =
                make_float4(acc[r][0], acc[r][1], acc[r][2], acc[r][3]);
    }
}

// ---------------- L1 aggregate + bias + relu + stats ----------------
template <int DOUT>
__global__ __launch_bounds__(256)
void aggregate_post_kernel(const float* __restrict__ m, const float* __restrict__ b,
                           float* __restrict__ out, int stat_off) {
    constexpr int NT  = DOUT / 4;
    constexpr int NPB = 256 / NT;
    __shared__ float s_sum[DOUT], s_sq[DOUT];
    int tid = threadIdx.x;
    for (int i = tid; i < DOUT; i += 256) { s_sum[i] = 0.f; s_sq[i] = 0.f; }
    __syncthreads();
    int lane = tid % NT;
    int node = blockIdx.x * NPB + tid / NT;
    const float4* m4 = (const float4*)m;
    if (node < NN) {
        float dn = g_dis[node];
        float sn = dn * dn;
        float a0 = b[lane*4+0], a1 = b[lane*4+1], a2 = b[lane*4+2], a3 = b[lane*4+3];
        float4 mv = __ldg(m4 + node * NT + lane);
        a0 += sn * mv.x; a1 += sn * mv.y; a2 += sn * mv.z; a3 += sn * mv.w;
        int e0 = node ? g_rowptr[node - 1] : 0;
        int e1 = g_rowptr[node];
        int e = e0;
        for (; e + 4 <= e1; e += 4) {
            int   sA = __ldg(&g_src[e]);     float wA = __ldg(&g_wn[e]);
            int   sB = __ldg(&g_src[e + 1]); float wB = __ldg(&g_wn[e + 1]);
            int   sC = __ldg(&g_src[e + 2]); float wC = __ldg(&g_wn[e + 2]);
            int   sD = __ldg(&g_src[e + 3]); float wD = __ldg(&g_wn[e + 3]);
            float4 vA = __ldg(m4 + sA * NT + lane);
            float4 vB = __ldg(m4 + sB * NT + lane);
            float4 vC = __ldg(m4 + sC * NT + lane);
            float4 vD = __ldg(m4 + sD * NT + lane);
            a0 += wA*vA.x + wB*vB.x + wC*vC.x + wD*vD.x;
            a1 += wA*vA.y + wB*vB.y + wC*vC.y + wD*vD.y;
            a2 += wA*vA.z + wB*vB.z + wC*vC.z + wD*vD.z;
            a3 += wA*vA.w + wB*vB.w + wC*vC.w + wD*vD.w;
        }
        for (; e < e1; e++) {
            int   s = __ldg(&g_src[e]);
            float w = __ldg(&g_wn[e]);
            float4 v = __ldg(m4 + s * NT + lane);
            a0 += w * v.x; a1 += w * v.y; a2 += w * v.z; a3 += w * v.w;
        }
        a0 = fmaxf(a0, 0.f); a1 = fmaxf(a1, 0.f);
        a2 = fmaxf(a2, 0.f); a3 = fmaxf(a3, 0.f);
        ((float4*)out)[node * NT + lane] = make_float4(a0, a1, a2, a3);
        atomicAdd(&s_sum[lane*4+0], a0); atomicAdd(&s_sq[lane*4+0], a0*a0);
        atomicAdd(&s_sum[lane*4+1], a1); atomicAdd(&s_sq[lane*4+1], a1*a1);
        atomicAdd(&s_sum[lane*4+2], a2); atomicAdd(&s_sq[lane*4+2], a2*a2);
        atomicAdd(&s_sum[lane*4+3], a3); atomicAdd(&s_sq[lane*4+3], a3*a3);
    }
    __syncthreads();
    for (int i = tid; i < DOUT; i += 256) {
        atomicAdd(&g_sum[stat_off + i], (double)s_sum[i]);
        atomicAdd(&g_sq[stat_off + i],  (double)s_sq[i]);
    }
}

// ---------------- fused: gather(BN-in) -> matmul -> bias(+relu) + stats ----------------
template <int DIN, int DOUT, int MODE_IN, bool RELU_OUT, int TILE, int TPN>
__global__ __launch_bounds__(512)
void fused_layer_kernel(const float* __restrict__ h, const float* __restrict__ W,
                        const float* __restrict__ bias, float* __restrict__ out,
                        const float* __restrict__ gamma, const float* __restrict__ beta,
                        int stat_in, int stat_out) {
    static_assert(TILE * TPN == 512, "gather must use all threads");
    constexpr int CG  = DOUT / 4;
    constexpr int RG  = 512 / CG;
    constexpr int RPT = TILE / RG;
    constexpr int F4  = DIN / 4 / TPN;
    extern __shared__ float smem[];
    float* sW = smem;                 // DIN*DOUT
    float* sH = smem + DIN * DOUT;    // TILE*DIN
    __shared__ float sS[DIN], sF[DIN];
    __shared__ float s_sum[DOUT], s_sq[DOUT];
    int t = threadIdx.x;
    if (t < DIN) {
        double mu  = g_sum[stat_in + t] / (double)NN;
        double var = g_sq[stat_in + t] / (double)NN - mu * mu;
        if (var < 0.0) var = 0.0;
        double sc = (double)gamma[t] * rsqrt(var + 1e-5);
        sS[t] = (float)sc;
        sF[t] = (float)((double)beta[t] - mu * sc);
    }
    for (int i = t; i < DOUT; i += 512) { s_sum[i] = 0.f; s_sq[i] = 0.f; }
    for (int i = t; i < DIN * DOUT / 4; i += 512)
        ((float4*)sW)[i] = ((const float4*)W)[i];
    __syncthreads();

    int node0 = blockIdx.x * TILE;
    // ---- gather phase ----
    {
        int local = t / TPN;
        int sub   = t % TPN;
        int base  = sub * F4;
        int node  = node0 + local;
        float a[F4][4];
        #pragma unroll
        for (int j = 0; j < F4; j++) { a[j][0]=0.f; a[j][1]=0.f; a[j][2]=0.f; a[j][3]=0.f; }
        if (node < NN) {
            const float4* h4 = (const float4*)h;
            float rs[F4][4], rf[F4][4];
            #pragma unroll
            for (int j = 0; j < F4; j++) {
                int c = (base + j) * 4;
                rs[j][0]=sS[c]; rs[j][1]=sS[c+1]; rs[j][2]=sS[c+2]; rs[j][3]=sS[c+3];
                rf[j][0]=sF[c]; rf[j][1]=sF[c+1]; rf[j][2]=sF[c+2]; rf[j][3]=sF[c+3];
            }
            auto accv = [&](const float4* v, float w) {
                #pragma unroll
                for (int j = 0; j < F4; j++) {
                    if (MODE_IN == 1) {
                        a[j][0] += w * fmaxf(rs[j][0]*v[j].x + rf[j][0], 0.f);
                        a[j][1] += w * fmaxf(rs[j][1]*v[j].y + rf[j][1], 0.f);
                        a[j][2] += w * fmaxf(rs[j][2]*v[j].z + rf[j][2], 0.f);
                        a[j][3] += w * fmaxf(rs[j][3]*v[j].w + rf[j][3], 0.f);
                    } else {
                        a[j][0] += w*v[j].x; a[j][1] += w*v[j].y;
                        a[j][2] += w*v[j].z; a[j][3] += w*v[j].w;
                    }
                }
            };
            float dn = g_dis[node];
            float sn = dn * dn;
            float wsum = sn;
            {
                float4 v[F4];
                #pragma unroll
                for (int j = 0; j < F4; j++) v[j] = __ldg(h4 + node * (DIN/4) + base + j);
                accv(v, sn);
            }
            int e0 = node ? g_rowptr[node - 1] : 0;
            int e1 = g_rowptr[node];
            int e = e0;
            for (; e + 4 <= e1; e += 4) {
                int   sA = __ldg(&g_src[e]);     float wA = __ldg(&g_wn[e]);
                int   sB = __ldg(&g_src[e + 1]); float wB = __ldg(&g_wn[e + 1]);
                int   sC = __ldg(&g_src[e + 2]); float wC = __ldg(&g_wn[e + 2]);
                int   sD = __ldg(&g_src[e + 3]); float wD = __ldg(&g_wn[e + 3]);
                float4 vA[F4], vB[F4], vC[F4], vD[F4];
                #pragma unroll
                for (int j = 0; j < F4; j++) vA[j] = __ldg(h4 + sA * (DIN/4) + base + j);
                #pragma unroll
                for (int j = 0; j < F4; j++) vB[j] = __ldg(h4 + sB * (DIN/4) + base + j);
                #pragma unroll
                for (int j = 0; j < F4; j++) vC[j] = __ldg(h4 + sC * (DIN/4) + base + j);
                #pragma unroll
                for (int j = 0; j < F4; j++) vD[j] = __ldg(h4 + sD * (DIN/4) + base + j);
                accv(vA, wA); accv(vB, wB); accv(vC, wC); accv(vD, wD);
                wsum += wA + wB + wC + wD;
            }
            for (; e < e1; e++) {
                int   s = __ldg(&g_src[e]);
                float w = __ldg(&g_wn[e]);
                float4 v[F4];
                #pragma unroll
                for (int j = 0; j < F4; j++) v[j] = __ldg(h4 + s * (DIN/4) + base + j);
                accv(v, w);
                wsum += w;
            }
            if (MODE_IN == 0) {
                #pragma unroll
                for (int j = 0; j < F4; j++) {
                    a[j][0] = rs[j][0]*a[j][0] + rf[j][0]*wsum;
                    a[j][1] = rs[j][1]*a[j][1] + rf[j][1]*wsum;
                    a[j][2] = rs[j][2]*a[j][2] + rf[j][2]*wsum;
                    a[j][3] = rs[j][3]*a[j][3] + rf[j][3]*wsum;
                }
            }
        }
        #pragma unroll
        for (int j = 0; j < F4; j++)
            ((float4*)sH)[local * (DIN / 4) + base + j] =
                make_float4(a[j][0], a[j][1], a[j][2], a[j][3]);
    }
    __syncthreads();

    // ---- matmul phase ----
    int cg = t % CG, rg = t / CG;
    float acc[RPT][4];
    #pragma unroll
    for (int r = 0; r < RPT; r++) { acc[r][0]=0.f; acc[r][1]=0.f; acc[r][2]=0.f; acc[r][3]=0.f; }
    const float* sHr = sH + rg * RPT * DIN;
    #pragma unroll 8
    for (int k = 0; k < DIN; k++) {
        float4 wv = *(const float4*)(sW + k * DOUT + cg * 4);
        #pragma unroll
        for (int r = 0; r < RPT; r++) {
            float hv = sHr[r * DIN + k];
            acc[r][0] += hv * wv.x; acc[r][1] += hv * wv.y;
            acc[r][2] += hv * wv.z; acc[r][3] += hv * wv.w;
        }
    }
    float b0 = bias[cg*4+0], b1 = bias[cg*4+1], b2 = bias[cg*4+2], b3 = bias[cg*4+3];
    float ls0=0.f, ls1=0.f, ls2=0.f, ls3=0.f, lq0=0.f, lq1=0.f, lq2=0.f, lq3=0.f;
    #pragma unroll
    for (int r = 0; r < RPT; r++) {
        int node = node0 + rg * RPT + r;
        if (node < NN) {
            float v0 = acc[r][0] + b0, v1 = acc[r][1] + b1;
            float v2 = acc[r][2] + b2, v3 = acc[r][3] + b3;
            if (RELU_OUT) {
                v0 = fmaxf(v0, 0.f); v1 = fmaxf(v1, 0.f);
                v2 = fmaxf(v2, 0.f); v3 = fmaxf(v3, 0.f);
            }
            ((float4*)out)[node * CG + cg] = make_float4(v0, v1, v2, v3);
            ls0 += v0; lq0 += v0*v0; ls1 += v1; lq1 += v1*v1;
            ls2 += v2; lq2 += v2*v2; ls3 += v3; lq3 += v3*v3;
        }
    }
    atomicAdd(&s_sum[cg*4+0], ls0); atomicAdd(&s_sq[cg*4+0], lq0);
    atomicAdd(&s_sum[cg*4+1], ls1); atomicAdd(&s_sq[cg*4+1], lq1);
    atomicAdd(&s_sum[cg*4+2], ls2); atomicAdd(&s_sq[cg*4+2], lq2);
    atomicAdd(&s_sum[cg*4+3], ls3); atomicAdd(&s_sq[cg*4+3], lq3);
    __syncthreads();
    for (int i = t; i < DOUT; i += 512) {
        atomicAdd(&g_sum[stat_out + i], (double)s_sum[i]);
        atomicAdd(&g_sq[stat_out + i],  (double)s_sq[i]);
    }
}

// ---------------- layer5 BN + global_add_pool ----------------
__global__ __launch_bounds__(256)
void pool_kernel(const float* __restrict__ h, const int* __restrict__ batch,
                 const float* __restrict__ gamma, const float* __restrict__ beta) {
    __shared__ float sScale[128], sShift[128];
    int t = threadIdx.x;
    if (t < 128) {
        double mu  = g_sum[512 + t] / (double)NN;
        double var = g_sq[512 + t] / (double)NN - mu * mu;
        if (var < 0.0) var = 0.0;
        double sc = (double)gamma[t] * rsqrt(var + 1e-5);
        sScale[t] = (float)sc;
        sShift[t] = (float)((double)beta[t] - mu * sc);
    }
    __syncthreads();
    constexpr int NODES = 64;
    int lane = t % 32;
    int grp  = t / 32;
    int base = blockIdx.x * NODES;
    float a0=0.f, a1=0.f, a2=0.f, a3=0.f;
    int cur = -1;
    float s0=sScale[lane*4+0], s1=sScale[lane*4+1], s2=sScale[lane*4+2], s3=sScale[lane*4+3];
    float h0=sShift[lane*4+0], h1=sShift[lane*4+1], h2=sShift[lane*4+2], h3=sShift[lane*4+3];
    for (int n = grp; n < NODES; n += 8) {
        int node = base + n;
        if (node >= NN) break;
        int bidx = batch[node];
        if (bidx != cur) {
            if (cur >= 0) {
                atomicAdd(&g_pooled[cur*128+lane*4+0], a0);
                atomicAdd(&g_pooled[cur*128+lane*4+1], a1);
                atomicAdd(&g_pooled[cur*128+lane*4+2], a2);
                atomicAdd(&g_pooled[cur*128+lane*4+3], a3);
            }
            cur = bidx; a0=a1=a2=a3=0.f;
        }
        float4 v = ((const float4*)h)[node * 32 + lane];
        a0 += s0*v.x + h0; a1 += s1*v.y + h1;
        a2 += s2*v.z + h2; a3 += s3*v.w + h3;
    }
    if (cur >= 0) {
        atomicAdd(&g_pooled[cur*128+lane*4+0], a0);
        atomicAdd(&g_pooled[cur*128+lane*4+1], a1);
        atomicAdd(&g_pooled[cur*128+lane*4+2], a2);
        atomicAdd(&g_pooled[cur*128+lane*4+3], a3);
    }
}

// ---------------- final MLP ----------------
__global__ void mlp_kernel(const float* __restrict__ fc1_w, const float* __restrict__ fc1_b,
                           const float* __restrict__ fc2_w, const float* __restrict__ fc2_b,
                           float* __restrict__ out) {
    int g = blockIdx.x;
    int t = threadIdx.x;  // 64
    __shared__ float sp[FMAX];
    for (int i = t; i < FMAX; i += 64) sp[i] = fmaxf(g_pooled[g * FMAX + i], 0.0f);
    __syncthreads();
    float acc = fc1_b[t];
    #pragma unroll 4
    for (int k = 0; k < FMAX; k++) acc += sp[k] * fc1_w[k * 64 + t];
    acc = fmaxf(acc, 0.0f);
    float v = acc * fc2_w[t];
    #pragma unroll
    for (int off = 16; off > 0; off >>= 1) v += __shfl_down_sync(0xffffffffu, v, off);
    __shared__ float red[2];
    if ((t & 31) == 0) red[t >> 5] = v;
    __syncthreads();
    if (t == 0) out[g] = red[0] + red[1] + fc2_b[0];
}

// ---------------- launch ----------------
extern "C" void kernel_launch(void* const* d_in, const int* in_sizes, int n_in,
                              void* d_out, int out_size) {
    const float* x     = (const float*)d_in[0];
    const int*   ei    = (const int*)d_in[1];
    const float* ew    = (const float*)d_in[2];
    const int*   batch = (const int*)d_in[3];
    const float *W1 = (const float*)d_in[4],  *b1 = (const float*)d_in[5],
                *g1 = (const float*)d_in[6],  *bt1 = (const float*)d_in[7];
    const float *W2 = (const float*)d_in[8],  *b2 = (const float*)d_in[9],
                *g2 = (const float*)d_in[10], *bt2 = (const float*)d_in[11];
    const float *W3 = (const float*)d_in[12], *b3 = (const float*)d_in[13],
                *g3 = (const float*)d_in[14], *bt3 = (const float*)d_in[15];
    const float *W4 = (const float*)d_in[16], *b4 = (const float*)d_in[17],
                *g4 = (const float*)d_in[18], *bt4 = (const float*)d_in[19];
    const float *W5 = (const float*)d_in[20], *b5 = (const float*)d_in[21],
                *g5 = (const float*)d_in[22], *bt5 = (const float*)d_in[23];
    const float* fc1_w = (const float*)d_in[24];
    const float* fc1_b = (const float*)d_in[25];
    const float* fc2_w = (const float*)d_in[26];
    const float* fc2_b = (const float*)d_in[27];
    float* out = (float*)d_out;

    float *bufA, *bufB, *bufM;
    cudaGetSymbolAddress((void**)&bufA, g_bufA);
    cudaGetSymbolAddress((void**)&bufB, g_bufB);
    cudaGetSymbolAddress((void**)&bufM, g_m);

    // opt-in smem for the L5 fused kernel (48KB dynamic + static > 48KB default)
    cudaFuncSetAttribute(
        (const void*)fused_layer_kernel<64, 128, 1, false, 64, 8>,
        cudaFuncAttributeMaxDynamicSharedMemorySize, 49152);

    const int TB = 256;
    init_kernel<<<(NN + TB - 1) / TB, TB>>>();
    count_kernel<<<(EE + TB - 1) / TB, TB>>>(ei, ew);
    csr_kernel<<<NB_SCAN, 1024>>>(ei, ew);

    auto smem = [](int din, int dout, int tile) {
        return (din * dout + tile * din) * 4;
    };

    // L1 (128->16)
    matmul_plain_kernel<128, 16, 64><<<(NN + 63) / 64, 256, smem(128, 16, 64)>>>(x, W1, bufM);
    aggregate_post_kernel<16><<<(NN * 4 + 255) / 256, 256>>>(bufM, b1, bufA, 0);
    // L2 (16->32)
    fused_layer_kernel<16, 32, 0, true, 128, 4><<<(NN + 127) / 128, 512, smem(16, 32, 128)>>>(
        bufA, W2, b2, bufB, g1, bt1, 0, 128);
    // L3 (32->64)
    fused_layer_kernel<32, 64, 0, true, 128, 4><<<(NN + 127) / 128, 512, smem(32, 64, 128)>>>(
        bufB, W3, b3, bufA, g2, bt2, 128, 256);
    // L4 (64->64)
    fused_layer_kernel<64, 64, 0, false, 64, 8><<<(NN + 63) / 64, 512, smem(64, 64, 64)>>>(
        bufA, W4, b4, bufB, g3, bt3, 256, 384);
    // L5 (64->128), full-width gather TILE=64
    fused_layer_kernel<64, 128, 1, false, 64, 8><<<(NN + 63) / 64, 512, smem(64, 128, 64)>>>(
        bufB, W5, b5, bufA, g4, bt4, 384, 512);

    pool_kernel<<<(NN + 63) / 64, 256>>>(bufA, batch, g5, bt5);
    mlp_kernel<<<GG, 64>>>(fc1_w, fc1_b, fc2_w, fc2_b, out);
}

// round 7
// speedup vs baseline: 1.0701x; 1.0701x over previous
#include <cuda_runtime.h>
#include <cuda_bf16.h>

#define NN 50000
#define EE 800000
#define GG 256
#define FMAX 128
#define NB_SCAN 49   // ceil(50000/1024)

// stat offsets: L1=0(16) L2=128(32) L3=256(64) L4=384(64) L5=512(128)
__device__ unsigned long long g_pack[NN];   // count<<42 | weightsum_fx32
__device__ float  g_dis[NN];
__device__ int    g_rowptr[NN + 1];
__device__ int    g_blocksum[64];
__device__ int    g_src[EE];
__device__ float  g_wn[EE];
__device__ float  g_bufA[NN * FMAX];
__device__ float  g_bufB[NN * 64];
__device__ float  g_m[NN * 16];
__device__ double g_sum[640];
__device__ double g_sq[640];
__device__ float  g_pooled[GG * FMAX];

// ---------------- preprocessing ----------------
__global__ void init_kernel() {
    int i = blockIdx.x * blockDim.x + threadIdx.x;
    if (i < NN) g_pack[i] = 0ULL;
    if (i < GG * FMAX) g_pooled[i] = 0.0f;
    if (i < 640) { g_sum[i] = 0.0; g_sq[i] = 0.0; }
}

__global__ void count_kernel(const int* __restrict__ ei, const float* __restrict__ ew) {
    int e = blockIdx.x * blockDim.x + threadIdx.x;
    if (e < EE) {
        int c = ei[EE + e];
        unsigned long long p = (1ULL << 42) |
            (unsigned long long)(ew[e] * 4294967296.0f);
        atomicAdd(&g_pack[c], p);
    }
}

// block-local scan; writes LOCAL exclusive starts + dis
__global__ void scan1_kernel() {
    __shared__ int s[1024];
    int t = threadIdx.x;
    int i = blockIdx.x * 1024 + t;
    unsigned long long p = (i < NN) ? g_pack[i] : 0ULL;
    int v = (int)(p >> 42);
    s[t] = v;
    if (i < NN) {
        double wfx = (double)(p & ((1ULL << 42) - 1ULL)) * 2.3283064365386963e-10;
        g_dis[i] = rsqrtf((float)(1.0 + wfx));
    }
    __syncthreads();
    #pragma unroll
    for (int off = 1; off < 1024; off <<= 1) {
        int x = (t >= off) ? s[t - off] : 0;
        __syncthreads();
        s[t] += x;
        __syncthreads();
    }
    if (i < NN) g_rowptr[i] = s[t] - v;   // local exclusive start
    if (t == 1023) g_blocksum[blockIdx.x] = s[1023];
}

// each block recomputes the 49-entry exclusive scan, adds its offset
__global__ void scanfix_kernel() {
    __shared__ int so[64];
    int t = threadIdx.x;
    if (t < 64) so[t] = (t >= 1 && t - 1 < NB_SCAN) ? g_blocksum[t - 1] : 0;
    __syncthreads();
    #pragma unroll
    for (int off = 1; off < 64; off <<= 1) {
        int x = (t < 64 && t >= off) ? so[t - off] : 0;
        __syncthreads();
        if (t < 64) so[t] += x;
        __syncthreads();
    }
    int add = so[blockIdx.x];
    int i = blockIdx.x * 1024 + t;
    if (i < NN) g_rowptr[i] += add;
}

// scatter; rowptr[c] doubles as fill cursor (post: rowptr[i] = end of node i)
__global__ void scatter_kernel(const int* __restrict__ ei, const float* __restrict__ ew) {
    int e = blockIdx.x * blockDim.x + threadIdx.x;
    if (e < EE) {
        int r = ei[e];
        int c = ei[EE + e];
        int pos = atomicAdd(&g_rowptr[c], 1);
        g_src[pos] = r;
        g_wn[pos]  = g_dis[r] * ew[e] * g_dis[c];
    }
}

// ---------------- L1 matmul: warp-per-node, W in registers, butterfly reduce ----------------
__global__ __launch_bounds__(256)
void matmul_l1_kernel(const float* __restrict__ x, const float* __restrict__ W1,
                      float* __restrict__ out) {
    int lane = threadIdx.x & 31;
    int gwarp = (blockIdx.x * 256 + threadIdx.x) >> 5;
    int nwarps = (gridDim.x * 256) >> 5;
    // lane owns W rows 4*lane .. 4*lane+3 (16 cols each) in registers
    float w[4][16];
    #pragma unroll
    for (int j = 0; j < 4; j++) {
        #pragma unroll
        for (int c = 0; c < 16; c += 4) {
            float4 v = __ldg((const float4*)(W1 + (lane * 4 + j) * 16 + c));
            w[j][c] = v.x; w[j][c+1] = v.y; w[j][c+2] = v.z; w[j][c+3] = v.w;
        }
    }
    for (int node = gwarp; node < NN; node += nwarps) {
        float4 xv = __ldg((const float4*)(x + node * 128 + lane * 4));
        float acc[16];
        #pragma unroll
        for (int c = 0; c < 16; c++)
            acc[c] = xv.x * w[0][c] + xv.y * w[1][c] + xv.z * w[2][c] + xv.w * w[3][c];
        // halving butterfly: 16 ch over 32 lanes; lane ends with ch = lane>>1
        #pragma unroll
        for (int r = 0; r < 4; r++) {
            const int off  = 16 >> r;   // 16,8,4,2
            const int nrem = 8 >> r;    // 8,4,2,1
            bool hi = (lane & off) != 0;
            #pragma unroll
            for (int j = 0; j < nrem; j++) {
                float send = hi ? acc[j] : acc[j + nrem];
                float keep = hi ? acc[j + nrem] : acc[j];
                acc[j] = keep + __shfl_xor_sync(0xffffffffu, send, off);
            }
        }
        acc[0] += __shfl_xor_sync(0xffffffffu, acc[0], 1);
        if (!(lane & 1)) out[node * 16 + (lane >> 1)] = acc[0];
    }
}

// ---------------- L1 aggregate + bias + relu + stats ----------------
template <int DOUT>
__global__ __launch_bounds__(256)
void aggregate_post_kernel(const float* __restrict__ m, const float* __restrict__ b,
                           float* __restrict__ out, int stat_off) {
    constexpr int NT  = DOUT / 4;
    constexpr int NPB = 256 / NT;
    __shared__ float s_sum[DOUT], s_sq[DOUT];
    int tid = threadIdx.x;
    for (int i = tid; i < DOUT; i += 256) { s_sum[i] = 0.f; s_sq[i] = 0.f; }
    __syncthreads();
    int lane = tid % NT;
    int node = blockIdx.x * NPB + tid / NT;
    const float4* m4 = (const float4*)m;
    if (node < NN) {
        float dn = g_dis[node];
        float sn = dn * dn;
        float a0 = b[lane*4+0], a1 = b[lane*4+1], a2 = b[lane*4+2], a3 = b[lane*4+3];
        float4 mv = __ldg(m4 + node * NT + lane);
        a0 += sn * mv.x; a1 += sn * mv.y; a2 += sn * mv.z; a3 += sn * mv.w;
        int e0 = node ? g_rowptr[node - 1] : 0;
        int e1 = g_rowptr[node];
        int e = e0;
        for (; e + 2 <= e1; e += 2) {
            int   sA = __ldg(&g_src[e]);     float wA = __ldg(&g_wn[e]);
            int   sB = __ldg(&g_src[e + 1]); float wB = __ldg(&g_wn[e + 1]);
            float4 vA = __ldg(m4 + sA * NT + lane);
            float4 vB = __ldg(m4 + sB * NT + lane);
            a0 += wA * vA.x; a1 += wA * vA.y; a2 += wA * vA.z; a3 += wA * vA.w;
            a0 += wB * vB.x; a1 += wB * vB.y; a2 += wB * vB.z; a3 += wB * vB.w;
        }
        if (e < e1) {
            int   s = __ldg(&g_src[e]);
            float w = __ldg(&g_wn[e]);
            float4 v = __ldg(m4 + s * NT + lane);
            a0 += w * v.x; a1 += w * v.y; a2 += w * v.z; a3 += w * v.w;
        }
        a0 = fmaxf(a0, 0.f); a1 = fmaxf(a1, 0.f);
        a2 = fmaxf(a2, 0.f); a3 = fmaxf(a3, 0.f);
        ((float4*)out)[node * NT + lane] = make_float4(a0, a1, a2, a3);
        atomicAdd(&s_sum[lane*4+0], a0); atomicAdd(&s_sq[lane*4+0], a0*a0);
        atomicAdd(&s_sum[lane*4+1], a1); atomicAdd(&s_sq[lane*4+1], a1*a1);
        atomicAdd(&s_sum[lane*4+2], a2); atomicAdd(&s_sq[lane*4+2], a2*a2);
        atomicAdd(&s_sum[lane*4+3], a3); atomicAdd(&s_sq[lane*4+3], a3*a3);
    }
    __syncthreads();
    for (int i = tid; i < DOUT; i += 256) {
        atomicAdd(&g_sum[stat_off + i], (double)s_sum[i]);
        atomicAdd(&g_sq[stat_off + i],  (double)s_sq[i]);
    }
}

// ---------------- fused: gather(BN-in) -> matmul -> bias(+relu) + stats ----------------
// MODE_IN 0: bn folded out of loop (a = s*agg + f*wsum); 1: relu(bn) per element.
template <int DIN, int DOUT, int MODE_IN, bool RELU_OUT, int TILE, int TPN>
__global__ __launch_bounds__(512)
void fused_layer_kernel(const float* __restrict__ h, const float* __restrict__ W,
                        const float* __restrict__ bias, float* __restrict__ out,
                        const float* __restrict__ gamma, const float* __restrict__ beta,
                        int stat_in, int stat_out) {
    constexpr int CG  = DOUT / 4;
    constexpr int RG  = 512 / CG;
    constexpr int RPT = TILE / RG;
    constexpr int F4  = DIN / 4 / TPN;
    extern __shared__ float smem[];
    float* sW = smem;                 // DIN*DOUT
    float* sH = smem + DIN * DOUT;    // TILE*DIN
    __shared__ float sS[DIN], sF[DIN];
    __shared__ float s_sum[DOUT], s_sq[DOUT];
    int t = threadIdx.x;
    if (t < DIN) {
        double mu  = g_sum[stat_in + t] / (double)NN;
        double var = g_sq[stat_in + t] / (double)NN - mu * mu;
        if (var < 0.0) var = 0.0;
        double sc = (double)gamma[t] * rsqrt(var + 1e-5);
        sS[t] = (float)sc;
        sF[t] = (float)((double)beta[t] - mu * sc);
    }
    for (int i = t; i < DOUT; i += 512) { s_sum[i] = 0.f; s_sq[i] = 0.f; }
    for (int i = t; i < DIN * DOUT / 4; i += 512)
        ((float4*)sW)[i] = ((const float4*)W)[i];
    __syncthreads();

    int node0 = blockIdx.x * TILE;
    // ---- gather phase ----
    if (t < TILE * TPN) {
        int local = t / TPN;
        int sub   = t % TPN;
        int base  = sub * F4;
        int node  = node0 + local;
        float a[F4][4];
        #pragma unroll
        for (int j = 0; j < F4; j++) { a[j][0]=0.f; a[j][1]=0.f; a[j][2]=0.f; a[j][3]=0.f; }
        if (node < NN) {
            const float4* h4 = (const float4*)h;
            float rs[F4][4], rf[F4][4];
            if (MODE_IN == 1) {
                #pragma unroll
                for (int j = 0; j < F4; j++) {
                    int c = (base + j) * 4;
                    rs[j][0]=sS[c]; rs[j][1]=sS[c+1]; rs[j][2]=sS[c+2]; rs[j][3]=sS[c+3];
                    rf[j][0]=sF[c]; rf[j][1]=sF[c+1]; rf[j][2]=sF[c+2]; rf[j][3]=sF[c+3];
                }
            }
            auto acc1 = [&](int s, float w) {
                #pragma unroll
                for (int j = 0; j < F4; j++) {
                    float4 v = __ldg(h4 + s * (DIN / 4) + base + j);
                    if (MODE_IN == 1) {
                        a[j][0] += w * fmaxf(rs[j][0]*v.x + rf[j][0], 0.f);
                        a[j][1] += w * fmaxf(rs[j][1]*v.y + rf[j][1], 0.f);
                        a[j][2] += w * fmaxf(rs[j][2]*v.z + rf[j][2], 0.f);
                        a[j][3] += w * fmaxf(rs[j][3]*v.w + rf[j][3], 0.f);
                    } else {
                        a[j][0] += w*v.x; a[j][1] += w*v.y; a[j][2] += w*v.z; a[j][3] += w*v.w;
                    }
                }
            };
            float dn = g_dis[node];
            float sn = dn * dn;
            float wsum = sn;
            acc1(node, sn);
            int e0 = node ? g_rowptr[node - 1] : 0;
            int e1 = g_rowptr[node];
            int e = e0;
            for (; e + 2 <= e1; e += 2) {
                int   sA = __ldg(&g_src[e]);     float wA = __ldg(&g_wn[e]);
                int   sB = __ldg(&g_src[e + 1]); float wB = __ldg(&g_wn[e + 1]);
                float4 vA[F4], vB[F4];
                #pragma unroll
                for (int j = 0; j < F4; j++) vA[j] = __ldg(h4 + sA * (DIN/4) + base + j);
                #pragma unroll
                for (int j = 0; j < F4; j++) vB[j] = __ldg(h4 + sB * (DIN/4) + base + j);
                #pragma unroll
                for (int j = 0; j < F4; j++) {
                    if (MODE_IN == 1) {
                        a[j][0] += wA * fmaxf(rs[j][0]*vA[j].x + rf[j][0], 0.f)
                                 + wB * fmaxf(rs[j][0]*vB[j].x + rf[j][0], 0.f);
                        a[j][1] += wA * fmaxf(rs[j][1]*vA[j].y + rf[j][1], 0.f)
                                 + wB * fmaxf(rs[j][1]*vB[j].y + rf[j][1], 0.f);
                        a[j][2] += wA * fmaxf(rs[j][2]*vA[j].z + rf[j][2], 0.f)
                                 + wB * fmaxf(rs[j][2]*vB[j].z + rf[j][2], 0.f);
                        a[j][3] += wA * fmaxf(rs[j][3]*vA[j].w + rf[j][3], 0.f)
                                 + wB * fmaxf(rs[j][3]*vB[j].w + rf[j][3], 0.f);
                    } else {
                        a[j][0] += wA*vA[j].x + wB*vB[j].x;
                        a[j][1] += wA*vA[j].y + wB*vB[j].y;
                        a[j][2] += wA*vA[j].z + wB*vB[j].z;
                        a[j][3] += wA*vA[j].w + wB*vB[j].w;
                    }
                }
                wsum += wA + wB;
            }
            if (e < e1) {
                int   s = __ldg(&g_src[e]);
                float w = __ldg(&g_wn[e]);
                acc1(s, w);
                wsum += w;
            }
            if (MODE_IN == 0) {
                #pragma unroll
                for (int j = 0; j < F4; j++) {
                    int c = (base + j) * 4;
                    a[j][0] = sS[c+0]*a[j][0] + sF[c+0]*wsum;
                    a[j][1] = sS[c+1]*a[j][1] + sF[c+1]*wsum;
                    a[j][2] = sS[c+2]*a[j][2] + sF[c+2]*wsum;
                    a[j][3] = sS[c+3]*a[j][3] + sF[c+3]*wsum;
                }
            }
        }
        #pragma unroll
        for (int j = 0; j < F4; j++)
            ((float4*)sH)[local * (DIN / 4) + base + j] =
                make_float4(a[j][0], a[j][1], a[j][2], a[j][3]);
    }
    __syncthreads();

    // ---- matmul phase ----
    int cg = t % CG, rg = t / CG;
    float acc[RPT][4];
    #pragma unroll
    for (int r = 0; r < RPT; r++) { acc[r][0]=0.f; acc[r][1]=0.f; acc[r][2]=0.f; acc[r][3]=0.f; }
    const float* sHr = sH + rg * RPT * DIN;
    #pragma unroll 8
    for (int k = 0; k < DIN; k++) {
        float4 wv = *(const float4*)(sW + k * DOUT + cg * 4);
        #pragma unroll
        for (int r = 0; r < RPT; r++) {
            float hv = sHr[r * DIN + k];
            acc[r][0] += hv * wv.x; acc[r][1] += hv * wv.y;
            acc[r][2] += hv * wv.z; acc[r][3] += hv * wv.w;
        }
    }
    float b0 = bias[cg*4+0], b1 = bias[cg*4+1], b2 = bias[cg*4+2], b3 = bias[cg*4+3];
    float ls0=0.f, ls1=0.f, ls2=0.f, ls3=0.f, lq0=0.f, lq1=0.f, lq2=0.f, lq3=0.f;
    #pragma unroll
    for (int r = 0; r < RPT; r++) {
        int node = node0 + rg * RPT + r;
        if (node < NN) {
            float v0 = acc[r][0] + b0, v1 = acc[r][1] + b1;
            float v2 = acc[r][2] + b2, v3 = acc[r][3] + b3;
            if (RELU_OUT) {
                v0 = fmaxf(v0, 0.f); v1 = fmaxf(v1, 0.f);
                v2 = fmaxf(v2, 0.f); v3 = fmaxf(v3, 0.f);
            }
            ((float4*)out)[node * CG + cg] = make_float4(v0, v1, v2, v3);
            ls0 += v0; lq0 += v0*v0; ls1 += v1; lq1 += v1*v1;
            ls2 += v2; lq2 += v2*v2; ls3 += v3; lq3 += v3*v3;
        }
    }
    atomicAdd(&s_sum[cg*4+0], ls0); atomicAdd(&s_sq[cg*4+0], lq0);
    atomicAdd(&s_sum[cg*4+1], ls1); atomicAdd(&s_sq[cg*4+1], lq1);
    atomicAdd(&s_sum[cg*4+2], ls2); atomicAdd(&s_sq[cg*4+2], lq2);
    atomicAdd(&s_sum[cg*4+3], ls3); atomicAdd(&s_sq[cg*4+3], lq3);
    __syncthreads();
    for (int i = t; i < DOUT; i += 512) {
        atomicAdd(&g_sum[stat_out + i], (double)s_sum[i]);
        atomicAdd(&g_sq[stat_out + i],  (double)s_sq[i]);
    }
}

// ---------------- layer5 BN + global_add_pool ----------------
__global__ __launch_bounds__(256)
void pool_kernel(const float* __restrict__ h, const int* __restrict__ batch,
                 const float* __restrict__ gamma, const float* __restrict__ beta) {
    __shared__ float sScale[128], sShift[128];
    int t = threadIdx.x;
    if (t < 128) {
        double mu  = g_sum[512 + t] / (double)NN;
        double var = g_sq[512 + t] / (double)NN - mu * mu;
        if (var < 0.0) var = 0.0;
        double sc = (double)gamma[t] * rsqrt(var + 1e-5);
        sScale[t] = (float)sc;
        sShift[t] = (float)((double)beta[t] - mu * sc);
    }
    __syncthreads();
    constexpr int NODES = 64;
    int lane = t % 32;
    int grp  = t / 32;
    int base = blockIdx.x * NODES;
    float a0=0.f, a1=0.f, a2=0.f, a3=0.f;
    int cur = -1;
    float s0=sScale[lane*4+0], s1=sScale[lane*4+1], s2=sScale[lane*4+2], s3=sScale[lane*4+3];
    float h0=sShift[lane*4+0], h1=sShift[lane*4+1], h2=sShift[lane*4+2], h3=sShift[lane*4+3];
    for (int n = grp; n < NODES; n += 8) {
        int node = base + n;
        if (node >= NN) break;
        int bidx = batch[node];
        if (bidx != cur) {
            if (cur >= 0) {
                atomicAdd(&g_pooled[cur*128+lane*4+0], a0);
                atomicAdd(&g_pooled[cur*128+lane*4+1], a1);
                atomicAdd(&g_pooled[cur*128+lane*4+2], a2);
                atomicAdd(&g_pooled[cur*128+lane*4+3], a3);
            }
            cur = bidx; a0=a1=a2=a3=0.f;
        }
        float4 v = ((const float4*)h)[node * 32 + lane];
        a0 += s0*v.x + h0; a1 += s1*v.y + h1;
        a2 += s2*v.z + h2; a3 += s3*v.w + h3;
    }
    if (cur >= 0) {
        atomicAdd(&g_pooled[cur*128+lane*4+0], a0);
        atomicAdd(&g_pooled[cur*128+lane*4+1], a1);
        atomicAdd(&g_pooled[cur*128+lane*4+2], a2);
        atomicAdd(&g_pooled[cur*128+lane*4+3], a3);
    }
}

// ---------------- final MLP ----------------
__global__ void mlp_kernel(const float* __restrict__ fc1_w, const float* __restrict__ fc1_b,
                           const float* __restrict__ fc2_w, const float* __restrict__ fc2_b,
                           float* __restrict__ out) {
    int g = blockIdx.x;
    int t = threadIdx.x;  // 64
    __shared__ float sp[FMAX];
    for (int i = t; i < FMAX; i += 64) sp[i] = fmaxf(g_pooled[g * FMAX + i], 0.0f);
    __syncthreads();
    float acc = fc1_b[t];
    #pragma unroll 4
    for (int k = 0; k < FMAX; k++) acc += sp[k] * fc1_w[k * 64 + t];
    acc = fmaxf(acc, 0.0f);
    float v = acc * fc2_w[t];
    #pragma unroll
    for (int off = 16; off > 0; off >>= 1) v += __shfl_down_sync(0xffffffffu, v, off);
    __shared__ float red[2];
    if ((t & 31) == 0) red[t >> 5] = v;
    __syncthreads();
    if (t == 0) out[g] = red[0] + red[1] + fc2_b[0];
}

// ---------------- launch ----------------
extern "C" void kernel_launch(void* const* d_in, const int* in_sizes, int n_in,
                              void* d_out, int out_size) {
    const float* x     = (const float*)d_in[0];
    const int*   ei    = (const int*)d_in[1];
    const float* ew    = (const float*)d_in[2];
    const int*   batch = (const int*)d_in[3];
    const float *W1 = (const float*)d_in[4],  *b1 = (const float*)d_in[5],
                *g1 = (const float*)d_in[6],  *bt1 = (const float*)d_in[7];
    const float *W2 = (const float*)d_in[8],  *b2 = (const float*)d_in[9],
                *g2 = (const float*)d_in[10], *bt2 = (const float*)d_in[11];
    const float *W3 = (const float*)d_in[12], *b3 = (const float*)d_in[13],
                *g3 = (const float*)d_in[14], *bt3 = (const float*)d_in[15];
    const float *W4 = (const float*)d_in[16], *b4 = (const float*)d_in[17],
                *g4 = (const float*)d_in[18], *bt4 = (const float*)d_in[19];
    const float *W5 = (const float*)d_in[20], *b5 = (const float*)d_in[21],
                *g5 = (const float*)d_in[22], *bt5 = (const float*)d_in[23];
    const float* fc1_w = (const float*)d_in[24];
    const float* fc1_b = (const float*)d_in[25];
    const float* fc2_w = (const float*)d_in[26];
    const float* fc2_b = (const float*)d_in[27];
    float* out = (float*)d_out;

    float *bufA, *bufB, *bufM;
    cudaGetSymbolAddress((void**)&bufA, g_bufA);
    cudaGetSymbolAddress((void**)&bufB, g_bufB);
    cudaGetSymbolAddress((void**)&bufM, g_m);

    const int TB = 256;
    init_kernel<<<(NN + TB - 1) / TB, TB>>>();
    count_kernel<<<(EE + TB - 1) / TB, TB>>>(ei, ew);
    scan1_kernel<<<NB_SCAN, 1024>>>();
    scanfix_kernel<<<NB_SCAN, 1024>>>();
    scatter_kernel<<<(EE + TB - 1) / TB, TB>>>(ei, ew);

    auto smem = [](int din, int dout, int tile) {
        return (din * dout + tile * din) * 4;
    };

    // L1 (128->16): warp-per-node matmul, then aggregate(bias,relu,stats@0)
    matmul_l1_kernel<<<592, 256>>>(x, W1, bufM);
    aggregate_post_kernel<16><<<(NN * 4 + 255) / 256, 256>>>(bufM, b1, bufA, 0);

    // L2 (16->32): gather(bn1 fold)+matmul+relu+stats@128 -> bufB(h2,32)
    fused_layer_kernel<16, 32, 0, true, 128, 4><<<(NN + 127) / 128, 512, smem(16, 32, 128)>>>(
        bufA, W2, b2, bufB, g1, bt1, 0, 128);
    // L3 (32->64): -> bufA(h3,64)
    fused_layer_kernel<32, 64, 0, true, 128, 4><<<(NN + 127) / 128, 512, smem(32, 64, 128)>>>(
        bufB, W3, b3, bufA, g2, bt2, 128, 256);
    // L4 (64->64): no relu-out -> bufB(c4,64)
    fused_layer_kernel<64, 64, 0, false, 64, 8><<<(NN + 63) / 64, 512, smem(64, 64, 64)>>>(
        bufA, W4, b4, bufB, g3, bt3, 256, 384);
    // L5 (64->128): gather relu(bn4) per element -> bufA(c5,128)
    fused_layer_kernel<64, 128, 1, false, 48, 8><<<(NN + 47) / 48, 512, smem(64, 128, 48)>>>(
        bufB, W5, b5, bufA, g4, bt4, 384, 512);

    // BN5 + pool, then MLP head
    pool_kernel<<<(NN + 63) / 64, 256>>>(bufA, batch, g5, bt5);
    mlp_kernel<<<GG, 64>>>(fc1_w, fc1_b, fc2_w, fc2_b, out);
}

// round 8
// speedup vs baseline: 1.0967x; 1.0249x over previous
#include <cuda_runtime.h>
#include <cuda_fp16.h>

#define NN 50000
#define EE 800000
#define GG 256
#define FMAX 128
#define NB_SCAN 49      // ceil(50000/1024)
#define NC_BLOCKS 3125  // ceil(EE/256)
#define MM_BLOCKS 592

// stat offsets: L1=0(16) L2=128(32) L3=256(64) L4=384(64) L5=512(128)
__device__ unsigned long long g_pack[NN];   // count<<42 | weightsum_fx32
__device__ float  g_dis[NN];
__device__ int    g_rowptr[NN + 1];
__device__ int    g_blocksum[64];
__device__ int    g_src[EE];
__device__ float  g_wn[EE];
__device__ float  g_bufA[NN * FMAX];   // h1(half16)/h3(half64)/c5(fp32 128)
__device__ float  g_bufB[NN * 64];     // h2(half32)/c4(half64)
__device__ float  g_m[NN * 16];        // L1 matmul out (fp32)
__device__ double g_sum[640];
__device__ double g_sq[640];
__device__ float  g_pooled[GG * FMAX];

// ---------------- preprocessing ----------------
__global__ void init_kernel() {
    int i = blockIdx.x * blockDim.x + threadIdx.x;
    if (i < NN) g_pack[i] = 0ULL;
    if (i < GG * FMAX) g_pooled[i] = 0.0f;
    if (i < 640) { g_sum[i] = 0.0; g_sq[i] = 0.0; }
}

// fused: blocks [0,NC) count edges; blocks [NC,NC+MM) do m = x @ W1 (independent)
__global__ __launch_bounds__(256)
void count_mm_kernel(const int* __restrict__ ei, const float* __restrict__ ew,
                     const float* __restrict__ x, const float* __restrict__ W1,
                     float* __restrict__ out) {
    if (blockIdx.x < NC_BLOCKS) {
        int e = blockIdx.x * 256 + threadIdx.x;
        if (e < EE) {
            int c = ei[EE + e];
            unsigned long long p = (1ULL << 42) |
                (unsigned long long)(ew[e] * 4294967296.0f);
            atomicAdd(&g_pack[c], p);
        }
        return;
    }
    // warp-per-node matmul, W1 in registers
    int lane = threadIdx.x & 31;
    int bid = blockIdx.x - NC_BLOCKS;
    int gwarp = (bid * 256 + threadIdx.x) >> 5;
    const int nwarps = MM_BLOCKS * 8;
    float w[4][16];
    #pragma unroll
    for (int j = 0; j < 4; j++) {
        #pragma unroll
        for (int c = 0; c < 16; c += 4) {
            float4 v = __ldg((const float4*)(W1 + (lane * 4 + j) * 16 + c));
            w[j][c] = v.x; w[j][c+1] = v.y; w[j][c+2] = v.z; w[j][c+3] = v.w;
        }
    }
    for (int node = gwarp; node < NN; node += nwarps) {
        float4 xv = __ldg((const float4*)(x + node * 128 + lane * 4));
        float acc[16];
        #pragma unroll
        for (int c = 0; c < 16; c++)
            acc[c] = xv.x * w[0][c] + xv.y * w[1][c] + xv.z * w[2][c] + xv.w * w[3][c];
        #pragma unroll
        for (int r = 0; r < 4; r++) {
            const int off  = 16 >> r;
            const int nrem = 8 >> r;
            bool hi = (lane & off) != 0;
            #pragma unroll
            for (int j = 0; j < nrem; j++) {
                float send = hi ? acc[j] : acc[j + nrem];
                float keep = hi ? acc[j + nrem] : acc[j];
                acc[j] = keep + __shfl_xor_sync(0xffffffffu, send, off);
            }
        }
        acc[0] += __shfl_xor_sync(0xffffffffu, acc[0], 1);
        if (!(lane & 1)) out[node * 16 + (lane >> 1)] = acc[0];
    }
}

__global__ void scan1_kernel() {
    __shared__ int s[1024];
    int t = threadIdx.x;
    int i = blockIdx.x * 1024 + t;
    unsigned long long p = (i < NN) ? g_pack[i] : 0ULL;
    int v = (int)(p >> 42);
    s[t] = v;
    if (i < NN) {
        double wfx = (double)(p & ((1ULL << 42) - 1ULL)) * 2.3283064365386963e-10;
        g_dis[i] = rsqrtf((float)(1.0 + wfx));
    }
    __syncthreads();
    #pragma unroll
    for (int off = 1; off < 1024; off <<= 1) {
        int x = (t >= off) ? s[t - off] : 0;
        __syncthreads();
        s[t] += x;
        __syncthreads();
    }
    if (i < NN) g_rowptr[i] = s[t] - v;
    if (t == 1023) g_blocksum[blockIdx.x] = s[1023];
}

__global__ void scanfix_kernel() {
    __shared__ int so[64];
    int t = threadIdx.x;
    if (t < 64) so[t] = (t >= 1 && t - 1 < NB_SCAN) ? g_blocksum[t - 1] : 0;
    __syncthreads();
    #pragma unroll
    for (int off = 1; off < 64; off <<= 1) {
        int x = (t < 64 && t >= off) ? so[t - off] : 0;
        __syncthreads();
        if (t < 64) so[t] += x;
        __syncthreads();
    }
    int add = so[blockIdx.x];
    int i = blockIdx.x * 1024 + t;
    if (i < NN) g_rowptr[i] += add;
}

__global__ void scatter_kernel(const int* __restrict__ ei, const float* __restrict__ ew) {
    int e = blockIdx.x * blockDim.x + threadIdx.x;
    if (e < EE) {
        int r = ei[e];
        int c = ei[EE + e];
        int pos = atomicAdd(&g_rowptr[c], 1);
        g_src[pos] = r;
        g_wn[pos]  = g_dis[r] * ew[e] * g_dis[c];
    }
}

// ---------------- L1 aggregate + bias + relu + stats -> half out ----------------
template <int DOUT>
__global__ __launch_bounds__(256)
void aggregate_post_kernel(const float* __restrict__ m, const float* __restrict__ b,
                           __half2* __restrict__ out, int stat_off) {
    constexpr int NT  = DOUT / 4;
    constexpr int NPB = 256 / NT;
    __shared__ float s_sum[DOUT], s_sq[DOUT];
    int tid = threadIdx.x;
    for (int i = tid; i < DOUT; i += 256) { s_sum[i] = 0.f; s_sq[i] = 0.f; }
    __syncthreads();
    int lane = tid % NT;
    int node = blockIdx.x * NPB + tid / NT;
    const float4* m4 = (const float4*)m;
    if (node < NN) {
        float dn = g_dis[node];
        float sn = dn * dn;
        float a0 = b[lane*4+0], a1 = b[lane*4+1], a2 = b[lane*4+2], a3 = b[lane*4+3];
        float4 mv = __ldg(m4 + node * NT + lane);
        a0 += sn * mv.x; a1 += sn * mv.y; a2 += sn * mv.z; a3 += sn * mv.w;
        int e0 = node ? g_rowptr[node - 1] : 0;
        int e1 = g_rowptr[node];
        int e = e0;
        for (; e + 2 <= e1; e += 2) {
            int   sA = __ldg(&g_src[e]);     float wA = __ldg(&g_wn[e]);
            int   sB = __ldg(&g_src[e + 1]); float wB = __ldg(&g_wn[e + 1]);
            float4 vA = __ldg(m4 + sA * NT + lane);
            float4 vB = __ldg(m4 + sB * NT + lane);
            a0 += wA * vA.x + wB * vB.x; a1 += wA * vA.y + wB * vB.y;
            a2 += wA * vA.z + wB * vB.z; a3 += wA * vA.w + wB * vB.w;
        }
        if (e < e1) {
            int   s = __ldg(&g_src[e]);
            float w = __ldg(&g_wn[e]);
            float4 v = __ldg(m4 + s * NT + lane);
            a0 += w * v.x; a1 += w * v.y; a2 += w * v.z; a3 += w * v.w;
        }
        a0 = fmaxf(a0, 0.f); a1 = fmaxf(a1, 0.f);
        a2 = fmaxf(a2, 0.f); a3 = fmaxf(a3, 0.f);
        out[node * (DOUT / 2) + lane * 2]     = __floats2half2_rn(a0, a1);
        out[node * (DOUT / 2) + lane * 2 + 1] = __floats2half2_rn(a2, a3);
        atomicAdd(&s_sum[lane*4+0], a0); atomicAdd(&s_sq[lane*4+0], a0*a0);
        atomicAdd(&s_sum[lane*4+1], a1); atomicAdd(&s_sq[lane*4+1], a1*a1);
        atomicAdd(&s_sum[lane*4+2], a2); atomicAdd(&s_sq[lane*4+2], a2*a2);
        atomicAdd(&s_sum[lane*4+3], a3); atomicAdd(&s_sq[lane*4+3], a3*a3);
    }
    __syncthreads();
    for (int i = tid; i < DOUT; i += 256) {
        atomicAdd(&g_sum[stat_off + i], (double)s_sum[i]);
        atomicAdd(&g_sq[stat_off + i],  (double)s_sq[i]);
    }
}

// ---------------- fused: gather(half in, BN) -> matmul -> bias(+relu) + stats ----------------
// MODE_IN 0: bn folded out of loop; 1: relu(bn) per element.
template <int DIN, int DOUT, int MODE_IN, bool RELU_OUT, int TILE, int TPN, bool OUT_HALF>
__global__ __launch_bounds__(512)
void fused_layer_kernel(const __half2* __restrict__ h, const float* __restrict__ W,
                        const float* __restrict__ bias, void* __restrict__ outv,
                        const float* __restrict__ gamma, const float* __restrict__ beta,
                        int stat_in, int stat_out) {
    constexpr int CG  = DOUT / 4;
    constexpr int RG  = 512 / CG;
    constexpr int RPT = TILE / RG;
    constexpr int DPT = DIN / TPN;   // dims per gather thread: 8 or 4
    constexpr int RS2 = DIN / 2;     // row stride in half2
    static_assert(TILE * TPN == 512, "gather uses all threads");
    static_assert(DPT == 8 || DPT == 4, "vector width");
    extern __shared__ float smem[];
    float* sW = smem;                 // DIN*DOUT
    float* sH = smem + DIN * DOUT;    // TILE*DIN
    __shared__ float sS[DIN], sF[DIN];
    __shared__ float s_sum[DOUT], s_sq[DOUT];
    int t = threadIdx.x;
    if (t < DIN) {
        double mu  = g_sum[stat_in + t] / (double)NN;
        double var = g_sq[stat_in + t] / (double)NN - mu * mu;
        if (var < 0.0) var = 0.0;
        double sc = (double)gamma[t] * rsqrt(var + 1e-5);
        sS[t] = (float)sc;
        sF[t] = (float)((double)beta[t] - mu * sc);
    }
    for (int i = t; i < DOUT; i += 512) { s_sum[i] = 0.f; s_sq[i] = 0.f; }
    for (int i = t; i < DIN * DOUT / 4; i += 512)
        ((float4*)sW)[i] = ((const float4*)W)[i];
    __syncthreads();

    int node0 = blockIdx.x * TILE;
    // ---- gather phase ----
    {
        int local = t / TPN;
        int sub   = t % TPN;
        int cbase = sub * DPT;
        int node  = node0 + local;
        float a[DPT];
        #pragma unroll
        for (int j = 0; j < DPT; j++) a[j] = 0.f;
        if (node < NN) {
            float rs[DPT], rf[DPT];
            #pragma unroll
            for (int j = 0; j < DPT; j++) { rs[j] = sS[cbase + j]; rf[j] = sF[cbase + j]; }
            auto loadrow = [&](int s, float* f) {
                const __half2* p = h + s * RS2 + (cbase >> 1);
                if (DPT == 8) {
                    uint4 raw = __ldg((const uint4*)p);
                    float2 t0 = __half22float2(*(__half2*)&raw.x);
                    float2 t1 = __half22float2(*(__half2*)&raw.y);
                    float2 t2 = __half22float2(*(__half2*)&raw.z);
                    float2 t3 = __half22float2(*(__half2*)&raw.w);
                    f[0] = t0.x; f[1] = t0.y; f[2] = t1.x; f[3] = t1.y;
                    f[4] = t2.x; f[5] = t2.y; f[6] = t3.x; f[7] = t3.y;
                } else {
                    uint2 raw = __ldg((const uint2*)p);
                    float2 t0 = __half22float2(*(__half2*)&raw.x);
                    float2 t1 = __half22float2(*(__half2*)&raw.y);
                    f[0] = t0.x; f[1] = t0.y; f[2] = t1.x; f[3] = t1.y;
                }
            };
            auto accum = [&](const float* f, float w) {
                #pragma unroll
                for (int j = 0; j < DPT; j++) {
                    float v = f[j];
                    if (MODE_IN == 1) v = fmaxf(rs[j] * v + rf[j], 0.f);
                    a[j] += w * v;
                }
            };
            float dn = g_dis[node];
            float sn = dn * dn;
            float wsum = sn;
            { float f[DPT]; loadrow(node, f); accum(f, sn); }
            int e0 = node ? g_rowptr[node - 1] : 0;
            int e1 = g_rowptr[node];
            int e = e0;
            for (; e + 2 <= e1; e += 2) {
                int   sA = __ldg(&g_src[e]);     float wA = __ldg(&g_wn[e]);
                int   sB = __ldg(&g_src[e + 1]); float wB = __ldg(&g_wn[e + 1]);
                float fA[DPT], fB[DPT];
                loadrow(sA, fA); loadrow(sB, fB);
                accum(fA, wA); accum(fB, wB);
                wsum += wA + wB;
            }
            if (e < e1) {
                int   s = __ldg(&g_src[e]);
                float w = __ldg(&g_wn[e]);
                float f[DPT]; loadrow(s, f); accum(f, w);
                wsum += w;
            }
            if (MODE_IN == 0) {
                #pragma unroll
                for (int j = 0; j < DPT; j++) a[j] = rs[j] * a[j] + rf[j] * wsum;
            }
        }
        #pragma unroll
        for (int j = 0; j < DPT; j += 4)
            ((float4*)sH)[(local * DIN + cbase + j) >> 2] =
                make_float4(a[j], a[j+1], a[j+2], a[j+3]);
    }
    __syncthreads();

    // ---- matmul phase ----
    int cg = t % CG, rg = t / CG;
    float acc[RPT][4];
    #pragma unroll
    for (int r = 0; r < RPT; r++) { acc[r][0]=0.f; acc[r][1]=0.f; acc[r][2]=0.f; acc[r][3]=0.f; }
    const float* sHr = sH + rg * RPT * DIN;
    #pragma unroll 8
    for (int k = 0; k < DIN; k++) {
        float4 wv = *(const float4*)(sW + k * DOUT + cg * 4);
        #pragma unroll
        for (int r = 0; r < RPT; r++) {
            float hv = sHr[r * DIN + k];
            acc[r][0] += hv * wv.x; acc[r][1] += hv * wv.y;
            acc[r][2] += hv * wv.z; acc[r][3] += hv * wv.w;
        }
    }
    float b0 = bias[cg*4+0], b1 = bias[cg*4+1], b2 = bias[cg*4+2], b3 = bias[cg*4+3];
    float ls0=0.f, ls1=0.f, ls2=0.f, ls3=0.f, lq0=0.f, lq1=0.f, lq2=0.f, lq3=0.f;
    #pragma unroll
    for (int r = 0; r < RPT; r++) {
        int node = node0 + rg * RPT + r;
        if (node < NN) {
            float v0 = acc[r][0] + b0, v1 = acc[r][1] + b1;
            float v2 = acc[r][2] + b2, v3 = acc[r][3] + b3;
            if (RELU_OUT) {
                v0 = fmaxf(v0, 0.f); v1 = fmaxf(v1, 0.f);
                v2 = fmaxf(v2, 0.f); v3 = fmaxf(v3, 0.f);
            }
            if (OUT_HALF) {
                __half2* o2 = (__half2*)outv;
                int idx = node * (DOUT / 2) + cg * 2;
                o2[idx]     = __floats2half2_rn(v0, v1);
                o2[idx + 1] = __floats2half2_rn(v2, v3);
            } else {
                ((float4*)outv)[node * CG + cg] = make_float4(v0, v1, v2, v3);
            }
            ls0 += v0; lq0 += v0*v0; ls1 += v1; lq1 += v1*v1;
            ls2 += v2; lq2 += v2*v2; ls3 += v3; lq3 += v3*v3;
        }
    }
    atomicAdd(&s_sum[cg*4+0], ls0); atomicAdd(&s_sq[cg*4+0], lq0);
    atomicAdd(&s_sum[cg*4+1], ls1); atomicAdd(&s_sq[cg*4+1], lq1);
    atomicAdd(&s_sum[cg*4+2], ls2); atomicAdd(&s_sq[cg*4+2], lq2);
    atomicAdd(&s_sum[cg*4+3], ls3); atomicAdd(&s_sq[cg*4+3], lq3);
    __syncthreads();
    for (int i = t; i < DOUT; i += 512) {
        atomicAdd(&g_sum[stat_out + i], (double)s_sum[i]);
        atomicAdd(&g_sq[stat_out + i],  (double)s_sq[i]);
    }
}

// ---------------- layer5 BN + global_add_pool ----------------
__global__ __launch_bounds__(256)
void pool_kernel(const float* __restrict__ h, const int* __restrict__ batch,
                 const float* __restrict__ gamma, const float* __restrict__ beta) {
    __shared__ float sScale[128], sShift[128];
    int t = threadIdx.x;
    if (t < 128) {
        double mu  = g_sum[512 + t] / (double)NN;
        double var = g_sq[512 + t] / (double)NN - mu * mu;
        if (var < 0.0) var = 0.0;
        double sc = (double)gamma[t] * rsqrt(var + 1e-5);
        sScale[t] = (float)sc;
        sShift[t] = (float)((double)beta[t] - mu * sc);
    }
    __syncthreads();
    constexpr int NODES = 64;
    int lane = t % 32;
    int grp  = t / 32;
    int base = blockIdx.x * NODES;
    float a0=0.f, a1=0.f, a2=0.f, a3=0.f;
    int cur = -1;
    float s0=sScale[lane*4+0], s1=sScale[lane*4+1], s2=sScale[lane*4+2], s3=sScale[lane*4+3];
    float h0=sShift[lane*4+0], h1=sShift[lane*4+1], h2=sShift[lane*4+2], h3=sShift[lane*4+3];
    for (int n = grp; n < NODES; n += 8) {
        int node = base + n;
        if (node >= NN) break;
        int bidx = batch[node];
        if (bidx != cur) {
            if (cur >= 0) {
                atomicAdd(&g_pooled[cur*128+lane*4+0], a0);
                atomicAdd(&g_pooled[cur*128+lane*4+1], a1);
                atomicAdd(&g_pooled[cur*128+lane*4+2], a2);
                atomicAdd(&g_pooled[cur*128+lane*4+3], a3);
            }
            cur = bidx; a0=a1=a2=a3=0.f;
        }
        float4 v = ((const float4*)h)[node * 32 + lane];
        a0 += s0*v.x + h0; a1 += s1*v.y + h1;
        a2 += s2*v.z + h2; a3 += s3*v.w + h3;
    }
    if (cur >= 0) {
        atomicAdd(&g_pooled[cur*128+lane*4+0], a0);
        atomicAdd(&g_pooled[cur*128+lane*4+1], a1);
        atomicAdd(&g_pooled[cur*128+lane*4+2], a2);
        atomicAdd(&g_pooled[cur*128+lane*4+3], a3);
    }
}

// ---------------- final MLP ----------------
__global__ void mlp_kernel(const float* __restrict__ fc1_w, const float* __restrict__ fc1_b,
                           const float* __restrict__ fc2_w, const float* __restrict__ fc2_b,
                           float* __restrict__ out) {
    int g = blockIdx.x;
    int t = threadIdx.x;  // 64
    __shared__ float sp[FMAX];
    for (int i = t; i < FMAX; i += 64) sp[i] = fmaxf(g_pooled[g * FMAX + i], 0.0f);
    __syncthreads();
    float acc = fc1_b[t];
    #pragma unroll 4
    for (int k = 0; k < FMAX; k++) acc += sp[k] * fc1_w[k * 64 + t];
    acc = fmaxf(acc, 0.0f);
    float v = acc * fc2_w[t];
    #pragma unroll
    for (int off = 16; off > 0; off >>= 1) v += __shfl_down_sync(0xffffffffu, v, off);
    __shared__ float red[2];
    if ((t & 31) == 0) red[t >> 5] = v;
    __syncthreads();
    if (t == 0) out[g] = red[0] + red[1] + fc2_b[0];
}

// ---------------- launch ----------------
extern "C" void kernel_launch(void* const* d_in, const int* in_sizes, int n_in,
                              void* d_out, int out_size) {
    const float* x     = (const float*)d_in[0];
    const int*   ei    = (const int*)d_in[1];
    const float* ew    = (const float*)d_in[2];
    const int*   batch = (const int*)d_in[3];
    const float *W1 = (const float*)d_in[4],  *b1 = (const float*)d_in[5],
                *g1 = (const float*)d_in[6],  *bt1 = (const float*)d_in[7];
    const float *W2 = (const float*)d_in[8],  *b2 = (const float*)d_in[9],
                *g2 = (const float*)d_in[10], *bt2 = (const float*)d_in[11];
    const float *W3 = (const float*)d_in[12], *b3 = (const float*)d_in[13],
                *g3 = (const float*)d_in[14], *bt3 = (const float*)d_in[15];
    const float *W4 = (const float*)d_in[16], *b4 = (const float*)d_in[17],
                *g4 = (const float*)d_in[18], *bt4 = (const float*)d_in[19];
    const float *W5 = (const float*)d_in[20], *b5 = (const float*)d_in[21],
                *g5 = (const float*)d_in[22], *bt5 = (const float*)d_in[23];
    const float* fc1_w = (const float*)d_in[24];
    const float* fc1_b = (const float*)d_in[25];
    const float* fc2_w = (const float*)d_in[26];
    const float* fc2_b = (const float*)d_in[27];
    float* out = (float*)d_out;

    float *bufA, *bufB, *bufM;
    cudaGetSymbolAddress((void**)&bufA, g_bufA);
    cudaGetSymbolAddress((void**)&bufB, g_bufB);
    cudaGetSymbolAddress((void**)&bufM, g_m);

    const int TB = 256;
    init_kernel<<<(NN + TB - 1) / TB, TB>>>();
    // count (edges) + L1 matmul (independent) in one launch
    count_mm_kernel<<<NC_BLOCKS + MM_BLOCKS, 256>>>(ei, ew, x, W1, bufM);
    scan1_kernel<<<NB_SCAN, 1024>>>();
    scanfix_kernel<<<NB_SCAN, 1024>>>();
    scatter_kernel<<<(EE + TB - 1) / TB, TB>>>(ei, ew);

    auto smem = [](int din, int dout, int tile) {
        return (din * dout + tile * din) * 4;
    };

    // L1 aggregate: m(fp32) -> h1(half16) in bufA
    aggregate_post_kernel<16><<<(NN * 4 + 255) / 256, 256>>>(bufM, b1, (__half2*)bufA, 0);

    // L2 (16->32): h1(half) -> h2(half) in bufB
    fused_layer_kernel<16, 32, 0, true, 256, 2, true>
        <<<(NN + 255) / 256, 512, smem(16, 32, 256)>>>(
        (const __half2*)bufA, W2, b2, bufB, g1, bt1, 0, 128);
    // L3 (32->64): h2 -> h3(half) in bufA
    fused_layer_kernel<32, 64, 0, true, 128, 4, true>
        <<<(NN + 127) / 128, 512, smem(32, 64, 128)>>>(
        (const __half2*)bufB, W3, b3, bufA, g2, bt2, 128, 256);
    // L4 (64->64): h3 -> c4(half) in bufB, no relu-out
    fused_layer_kernel<64, 64, 0, false, 64, 8, true>
        <<<(NN + 63) / 64, 512, smem(64, 64, 64)>>>(
        (const __half2*)bufA, W4, b4, bufB, g3, bt3, 256, 384);
    // L5 (64->128): gather relu(bn(c4)) -> c5(fp32) in bufA
    fused_layer_kernel<64, 128, 1, false, 32, 16, false>
        <<<(NN + 31) / 32, 512, smem(64, 128, 32)>>>(
        (const __half2*)bufB, W5, b5, bufA, g4, bt4, 384, 512);

    // BN5 + pool, then MLP head
    pool_kernel<<<(NN + 63) / 64, 256>>>(bufA, batch, g5, bt5);
    mlp_kernel<<<GG, 64>>>(fc1_w, fc1_b, fc2_w, fc2_b, out);
}